// round 16
// baseline (speedup 1.0000x reference)
#include <cuda_runtime.h>
#include <cuda_bf16.h>
#include <cstdint>

#define NC 16
#define HWSZ (512*512)
#define NPIX (4*HWSZ)
#define ST_TOTAL (NPIX/32)      // 32768 super-tiles of 32 pixels
#define GRID 296                // 2 CTAs per SM
#define NW (GRID*8)             // 2368 warps total

// ---------------- folded weights (device globals) ---------------------------
__device__ float g_e1[16 * 64];
__device__ float g_e2[16 * 64];
__device__ float g_c1[128];
__device__ float g_c2[16];
__device__ __nv_bfloat16 g_W1T[128 * 32];   // [j][k]: k<16 -> W0@fw ; k>=16 -> Magg + c1 (bias folded)
__device__ __nv_bfloat16 g_W2T[16 * 144];   // [n][k]: k<128 -> ow@W1 ; k>=128 -> ow@Magg + c2
// pre-swizzled per-lane mma fragments (written by setup_y warp 0)
__device__ __align__(16) uint32_t g_W1F[8][32][8];
__device__ __align__(16) uint32_t g_W2F[8][32][4];
__device__ __align__(16) uint32_t g_SF[32][4];

// ---------------- helpers ---------------------------------------------------
__device__ __forceinline__ uint32_t sptr(const void* p) {
    return (uint32_t)__cvta_generic_to_shared(p);
}
__device__ __forceinline__ void ldm4(uint32_t& r0, uint32_t& r1, uint32_t& r2, uint32_t& r3,
                                     uint32_t addr) {
    asm volatile("ldmatrix.sync.aligned.m8n8.x4.shared.b16 {%0,%1,%2,%3}, [%4];"
                 : "=r"(r0), "=r"(r1), "=r"(r2), "=r"(r3) : "r"(addr));
}
__device__ __forceinline__ void mma16816(float* c, const uint32_t* a, uint32_t b0, uint32_t b1) {
    asm volatile("mma.sync.aligned.m16n8k16.row.col.f32.bf16.bf16.f32 "
                 "{%0,%1,%2,%3}, {%4,%5,%6,%7}, {%8,%9}, {%0,%1,%2,%3};"
                 : "+f"(c[0]), "+f"(c[1]), "+f"(c[2]), "+f"(c[3])
                 : "r"(a[0]), "r"(a[1]), "r"(a[2]), "r"(a[3]), "r"(b0), "r"(b1));
}
__device__ __forceinline__ uint32_t pack2(float a, float b) {
    __nv_bfloat162 h = __floats2bfloat162_rn(a, b);
    return *reinterpret_cast<uint32_t*>(&h);
}
__device__ __forceinline__ uint32_t packrelu2(float a, float b) {
    return pack2(fmaxf(a, 0.0f), fmaxf(b, 0.0f));
}
__device__ __forceinline__ float wred(float s) {
    #pragma unroll
    for (int d = 16; d > 0; d >>= 1) s += __shfl_xor_sync(0xffffffffu, s, d);
    return s;
}

// ---------------- setup_x: maximally parallel folds (337 CTAs) --------------
__global__ __launch_bounds__(256)
void setup_x(const float* __restrict__ E,
             const float* __restrict__ aw1, const float* __restrict__ ab1,
             const float* __restrict__ aw2, const float* __restrict__ ab2,
             const float* __restrict__ w0,  const float* __restrict__ b0,
             const float* __restrict__ w1,  const float* __restrict__ b1,
             const float* __restrict__ fw,  const float* __restrict__ fb,
             const float* __restrict__ ow,  const float* __restrict__ ob) {
    const int tid = threadIdx.x;
    const int lane = tid & 31;
    const int w = tid >> 5;
    const int blk = blockIdx.x;

    if (blk < 256) {
        const int wid = (blk << 3) | w;              // 0..2047
        const int which = wid >> 10, i = (wid >> 6) & 15, k = wid & 63;
        const float* __restrict__ wp = which ? aw2 : aw1;
        const float4 ev = *reinterpret_cast<const float4*>(E + i * 128 + 4 * lane);
        const float4 wv = *reinterpret_cast<const float4*>(wp + k * 128 + 4 * lane);
        const float s = wred(ev.x * wv.x + ev.y * wv.y + ev.z * wv.z + ev.w * wv.w);
        if (lane == 0) {
            const float v = fmaxf(s + (which ? ab2 : ab1)[k], 0.0f);
            if (which) g_e2[i * 64 + k] = v; else g_e1[i * 64 + k] = v;
        }
    } else if (blk < 288) {
        // Bw = ow @ W1 -> g_W2T cols 0..127
        const int tg = (blk - 256) * 256 + tid;
        const int o = tg >> 2, sub = tg & 3;
        const int n = o >> 7, d = o & 127;
        const float* __restrict__ owr = ow + n * 128 + sub * 32;
        float s0 = 0.f, s1 = 0.f;
        #pragma unroll 8
        for (int j = 0; j < 32; j += 2) {
            s0 += owr[j]     * w1[(sub * 32 + j)     * 128 + d];
            s1 += owr[j + 1] * w1[(sub * 32 + j + 1) * 128 + d];
        }
        float s = s0 + s1;
        s += __shfl_xor_sync(0xffffffffu, s, 1);
        s += __shfl_xor_sync(0xffffffffu, s, 2);
        if (sub == 0) g_W2T[n * 144 + d] = __float2bfloat16(s);
    } else if (blk < 320) {
        // A = W0 @ fw -> g_W1T cols 0..15
        const int tg = (blk - 288) * 256 + tid;
        const int o = tg >> 2, sub = tg & 3;
        const int j = o >> 4, c = o & 15;
        const float* __restrict__ wr = w0 + j * 128 + sub * 32;
        float s0 = 0.f, s1 = 0.f;
        #pragma unroll 8
        for (int d = 0; d < 32; d += 2) {
            s0 += wr[d]     * fw[(sub * 32 + d)     * 16 + c];
            s1 += wr[d + 1] * fw[(sub * 32 + d + 1) * 16 + c];
        }
        float s = s0 + s1;
        s += __shfl_xor_sync(0xffffffffu, s, 1);
        s += __shfl_xor_sync(0xffffffffu, s, 2);
        if (sub == 0) g_W1T[j * 32 + c] = __float2bfloat16(s);
    } else if (blk < 336) {
        const int j = ((blk - 320) << 3) | w;        // 0..127
        const float4 wv = *reinterpret_cast<const float4*>(&w0[j * 128 + 4 * lane]);
        const float4 fv = *reinterpret_cast<const float4*>(&fb[4 * lane]);
        const float s = wred(wv.x * fv.x + wv.y * fv.y + wv.z * fv.z + wv.w * fv.w);
        if (lane == 0) g_c1[j] = s + b0[j];
    } else {
        for (int r = 0; r < 2; r++) {
            const int n = w * 2 + r;
            const float4 ov = *reinterpret_cast<const float4*>(&ow[n * 128 + 4 * lane]);
            const float4 bv = *reinterpret_cast<const float4*>(&b1[4 * lane]);
            const float s = wred(ov.x * bv.x + ov.y * bv.y + ov.z * bv.z + ov.w * bv.w);
            if (lane == 0) g_c2[n] = s + ob[n];
        }
    }
}

// ---------------- setup_y: adjacency + bias folds + fragment repack ---------
__global__ __launch_bounds__(256)
void setup_y(const float* __restrict__ E, const float* __restrict__ ow) {
    __shared__ float e1s[16][64];
    __shared__ float e2s[16][64];
    __shared__ float adjs[16][16];
    __shared__ float rs[16];
    __shared__ float Maggs[128][16];
    __shared__ __align__(16) __nv_bfloat16 W1s[128][40];
    __shared__ __align__(16) __nv_bfloat16 W2s[16][152];
    const int tid = threadIdx.x;

    for (int i = tid; i < 1024; i += 256) {
        e1s[i >> 6][i & 63] = g_e1[i];
        e2s[i >> 6][i & 63] = g_e2[i];
    }
    __syncthreads();
    {
        const int i = tid >> 4, j = tid & 15;
        float s0 = 0.f, s1 = 0.f, s2 = 0.f, s3 = 0.f;
        #pragma unroll 4
        for (int k = 0; k < 64; k += 4) {
            s0 += e1s[i][k]     * e2s[j][k];
            s1 += e1s[i][k + 1] * e2s[j][k + 1];
            s2 += e1s[i][k + 2] * e2s[j][k + 2];
            s3 += e1s[i][k + 3] * e2s[j][k + 3];
        }
        const float s = (s0 + s1) + (s2 + s3);
        adjs[i][j] = 1.0f / (1.0f + expf(-s)) + ((i == j) ? 1.0f : 0.0f);
    }
    __syncthreads();
    if (tid < 16) {
        float s = 0.0f;
        #pragma unroll
        for (int j = 0; j < 16; j++) s += adjs[tid][j];
        rs[tid] = 1.0f / s;
    }
    __syncthreads();
    // Magg + c1 fold -> W1T cols 16..31 (exact: sum_c p_c = 1); keep Magg for S
    for (int idx = tid; idx < 2048; idx += 256) {
        const int c = idx >> 7, j = idx & 127;
        float s = 0.0f;
        #pragma unroll
        for (int i = 0; i < 16; i++) s += adjs[c][i] * E[i * 128 + j];
        s *= rs[c];
        Maggs[j][c] = s;
        const __nv_bfloat16 hb = __float2bfloat16(s + g_c1[j]);
        g_W1T[j * 32 + 16 + c] = hb;
        W1s[j][16 + c] = hb;
    }
    __syncthreads();
    // S + c2 fold -> W2T cols 128..143
    {
        const int n = tid >> 4, c = tid & 15;
        float s0 = 0.f, s1 = 0.f, s2 = 0.f, s3 = 0.f;
        #pragma unroll 4
        for (int j = 0; j < 128; j += 4) {
            s0 += ow[n * 128 + j]     * Maggs[j][c];
            s1 += ow[n * 128 + j + 1] * Maggs[j + 1][c];
            s2 += ow[n * 128 + j + 2] * Maggs[j + 2][c];
            s3 += ow[n * 128 + j + 3] * Maggs[j + 3][c];
        }
        const __nv_bfloat16 hb = __float2bfloat16((s0 + s1) + (s2 + s3) + g_c2[n]);
        g_W2T[n * 144 + 128 + c] = hb;
        W2s[n][128 + c] = hb;
    }
    // stage setup_x-produced parts (global writes visible after kernel-ordering)
    for (int i = tid; i < 2048; i += 256) {          // W1T cols 0..15
        const int j = i >> 4, c = i & 15;
        W1s[j][c] = g_W1T[j * 32 + c];
    }
    for (int i = tid; i < 2048; i += 256) {          // W2T cols 0..127
        const int n = i >> 7, d = i & 127;
        W2s[n][d] = g_W2T[n * 144 + d];
    }
    __syncthreads();

    // ---- warp 0: ldmatrix repack -> per-lane fragment arrays in gmem ----
    if (tid < 32) {
        const int lane = tid;
        const int brow16 = (lane & 7) + ((lane >= 16) ? 8 : 0);
        const int bcol8 = (lane & 8) ? 8 : 0;
        #pragma unroll
        for (int ntp = 0; ntp < 8; ntp++) {
            uint32_t r0, r1, r2, r3;
            ldm4(r0, r1, r2, r3, sptr(&W1s[16 * ntp + brow16][bcol8]));
            g_W1F[ntp][lane][0] = r0; g_W1F[ntp][lane][1] = r1;
            g_W1F[ntp][lane][2] = r2; g_W1F[ntp][lane][3] = r3;
            ldm4(r0, r1, r2, r3, sptr(&W1s[16 * ntp + brow16][16 + bcol8]));
            g_W1F[ntp][lane][4] = r0; g_W1F[ntp][lane][5] = r1;
            g_W1F[ntp][lane][6] = r2; g_W1F[ntp][lane][7] = r3;
        }
        #pragma unroll
        for (int kb = 0; kb < 8; kb++) {
            uint32_t r0, r1, r2, r3;
            ldm4(r0, r1, r2, r3, sptr(&W2s[brow16][16 * kb + bcol8]));
            g_W2F[kb][lane][0] = r0; g_W2F[kb][lane][1] = r1;
            g_W2F[kb][lane][2] = r2; g_W2F[kb][lane][3] = r3;
        }
        uint32_t r0, r1, r2, r3;
        ldm4(r0, r1, r2, r3, sptr(&W2s[brow16][128 + bcol8]));
        g_SF[lane][0] = r0; g_SF[lane][1] = r1;
        g_SF[lane][2] = r2; g_SF[lane][3] = r3;
    }
}

// ---------------- refine: 32-px super-tiles, zero CTA barriers --------------
__global__ __launch_bounds__(256, 2)
void refine_kernel(const float* __restrict__ logits, float* __restrict__ out,
                   const float* __restrict__ gatep) {
    // per-warp 16ch x 32px fp32 slab, row stride 36 (conflict-free frag reads)
    __shared__ __align__(16) float wbuf[8][2][16 * 36];   // 36864 B total
    const int tid = threadIdx.x;
    const int lane = tid & 31;
    const int w = tid >> 5;
    const int t = lane & 3;
    const int g = lane >> 2;
    const int ldr = lane >> 3;       // row offset 0..3 for 128B loads/stores
    const int ldc = (lane & 7) * 4;  // 16B chunk within 128B row

    const float gate = *gatep;

    // weight fragments via LDG (L1-broadcast; no smem, no barriers)
    uint32_t fW1[8][8];
    #pragma unroll
    for (int kb = 0; kb < 8; kb++) {
        const uint4 u0 = *reinterpret_cast<const uint4*>(&g_W1F[kb][lane][0]);
        const uint4 u1 = *reinterpret_cast<const uint4*>(&g_W1F[kb][lane][4]);
        fW1[kb][0] = u0.x; fW1[kb][1] = u0.y; fW1[kb][2] = u0.z; fW1[kb][3] = u0.w;
        fW1[kb][4] = u1.x; fW1[kb][5] = u1.y; fW1[kb][6] = u1.z; fW1[kb][7] = u1.w;
    }
    uint32_t fS[4];
    {
        const uint4 u = *reinterpret_cast<const uint4*>(&g_SF[lane][0]);
        fS[0] = u.x; fS[1] = u.y; fS[2] = u.z; fS[3] = u.w;
    }

    // per-warp prefetch: 16 channel-rows x 128B, 4 cp.async of 16B/lane
    auto prefetch = [&](int st_, int bsel) {
        const int P = st_ << 5;
        const float* __restrict__ src =
            logits + (size_t)(P >> 18) * (NC * HWSZ) + (P & (HWSZ - 1));
        #pragma unroll
        for (int i = 0; i < 4; i++) {
            const int r = 4 * i + ldr;
            const uint32_t d = sptr(&wbuf[w][bsel][r * 36 + ldc]);
            const float* s = src + (size_t)r * HWSZ + ldc;
            asm volatile("cp.async.cg.shared.global [%0], [%1], 16;" :: "r"(d), "l"(s));
        }
        asm volatile("cp.async.commit_group;");
    };

    int st = (blockIdx.x << 3) | w;
    prefetch(st, 0);
    {
        int t1 = st + NW; if (t1 >= ST_TOTAL) t1 = st;
        prefetch(t1, 1);
    }
    int buf = 0;

    for (; st < ST_TOTAL; st += NW) {
        asm volatile("cp.async.wait_group 1;");
        __syncwarp();
        float* __restrict__ B = &wbuf[w][buf][0];

        // ---- two 16-px tiles, processed sequentially ----
        #pragma unroll
        for (int half = 0; half < 2; half++) {
            const int po = half * 16 + g;
            const float l0 = B[(2 * t) * 36 + po],         l1 = B[(2 * t + 1) * 36 + po];
            const float l2 = B[(2 * t) * 36 + po + 8],     l3 = B[(2 * t + 1) * 36 + po + 8];
            const float l4 = B[(2 * t + 8) * 36 + po],     l5 = B[(2 * t + 9) * 36 + po];
            const float l6 = B[(2 * t + 8) * 36 + po + 8], l7 = B[(2 * t + 9) * 36 + po + 8];
            // softmax, no max-sub (logits O(1), fp32-safe, identical)
            const float p0 = __expf(l0), p1 = __expf(l1);
            const float p4 = __expf(l4), p5 = __expf(l5);
            const float q2 = __expf(l2), q3 = __expf(l3);
            const float q6 = __expf(l6), q7 = __expf(l7);
            float sx = (p0 + p1) + (p4 + p5);
            float sy = (q2 + q3) + (q6 + q7);
            sx += __shfl_xor_sync(0xffffffffu, sx, 1);
            sy += __shfl_xor_sync(0xffffffffu, sy, 1);
            sx += __shfl_xor_sync(0xffffffffu, sx, 2);
            sy += __shfl_xor_sync(0xffffffffu, sy, 2);
            const float ix = __fdividef(1.0f, sx);
            const float iy = __fdividef(1.0f, sy);
            uint32_t aL[4], aP[4];
            aL[0] = pack2(l0, l1); aL[1] = pack2(l2, l3);
            aL[2] = pack2(l4, l5); aL[3] = pack2(l6, l7);
            aP[0] = pack2(p0 * ix, p1 * ix); aP[1] = pack2(q2 * iy, q3 * iy);
            aP[2] = pack2(p4 * ix, p5 * ix); aP[3] = pack2(q6 * iy, q7 * iy);

            // GEMM1 -> relu -> GEMM2 (biases pre-folded, acc init 0)
            float racc[2][4] = {{0.f, 0.f, 0.f, 0.f}, {0.f, 0.f, 0.f, 0.f}};
            mma16816(racc[0], aP, fS[0], fS[1]);
            mma16816(racc[1], aP, fS[2], fS[3]);
            #pragma unroll
            for (int kb = 0; kb < 8; kb++) {
                const uint4 bv = *reinterpret_cast<const uint4*>(&g_W2F[kb][lane][0]);
                float acc0[4] = {0.f, 0.f, 0.f, 0.f};
                float acc1[4] = {0.f, 0.f, 0.f, 0.f};
                mma16816(acc0, aL, fW1[kb][0], fW1[kb][1]);
                mma16816(acc1, aL, fW1[kb][2], fW1[kb][3]);
                mma16816(acc0, aP, fW1[kb][4], fW1[kb][5]);
                mma16816(acc1, aP, fW1[kb][6], fW1[kb][7]);
                uint32_t h[4];
                h[0] = packrelu2(acc0[0], acc0[1]);
                h[1] = packrelu2(acc0[2], acc0[3]);
                h[2] = packrelu2(acc1[0], acc1[1]);
                h[3] = packrelu2(acc1[2], acc1[3]);
                mma16816(racc[0], h, bv.x, bv.y);
                mma16816(racc[1], h, bv.z, bv.w);
            }

            // epilogue: gate*r + residual (l still live) back into slab
            B[(2 * t) * 36 + po]         = fmaf(gate, racc[0][0], l0);
            B[(2 * t + 1) * 36 + po]     = fmaf(gate, racc[0][1], l1);
            B[(2 * t) * 36 + po + 8]     = fmaf(gate, racc[0][2], l2);
            B[(2 * t + 1) * 36 + po + 8] = fmaf(gate, racc[0][3], l3);
            B[(2 * t + 8) * 36 + po]     = fmaf(gate, racc[1][0], l4);
            B[(2 * t + 9) * 36 + po]     = fmaf(gate, racc[1][1], l5);
            B[(2 * t + 8) * 36 + po + 8] = fmaf(gate, racc[1][2], l6);
            B[(2 * t + 9) * 36 + po + 8] = fmaf(gate, racc[1][3], l7);
        }
        __syncwarp();

        // ---- coalesced store: 16 channel-rows x 128B ----
        {
            const int P = st << 5;
            float* __restrict__ dst =
                out + (size_t)(P >> 18) * (NC * HWSZ) + (P & (HWSZ - 1));
            #pragma unroll
            for (int i = 0; i < 4; i++) {
                const int r = 4 * i + ldr;
                const float4 v = *reinterpret_cast<const float4*>(B + r * 36 + ldc);
                *reinterpret_cast<float4*>(dst + (size_t)r * HWSZ + ldc) = v;
            }
        }

        // refill this slab (reads above already consumed into registers)
        {
            int n2 = st + 2 * NW; if (n2 >= ST_TOTAL) n2 = st;
            prefetch(n2, buf);
        }
        buf ^= 1;
    }
}

// ---------------- launch -----------------------------------------------------
extern "C" void kernel_launch(void* const* d_in, const int* in_sizes, int n_in,
                              void* d_out, int out_size) {
    const float* logits = (const float*)d_in[0];
    const float* E      = (const float*)d_in[1];
    const float* aw1    = (const float*)d_in[2];
    const float* ab1    = (const float*)d_in[3];
    const float* aw2    = (const float*)d_in[4];
    const float* ab2    = (const float*)d_in[5];
    const float* w0     = (const float*)d_in[6];
    const float* b0     = (const float*)d_in[7];
    const float* w1     = (const float*)d_in[8];
    const float* b1     = (const float*)d_in[9];
    const float* fw     = (const float*)d_in[10];
    const float* fb     = (const float*)d_in[11];
    const float* ow     = (const float*)d_in[12];
    const float* ob     = (const float*)d_in[13];
    const float* gate   = (const float*)d_in[14];
    float* out = (float*)d_out;

    setup_x<<<337, 256>>>(E, aw1, ab1, aw2, ab2, w0, b0, w1, b1, fw, fb, ow, ob);
    setup_y<<<1, 256>>>(E, ow);
    refine_kernel<<<GRID, 256>>>(logits, out, gate);
}

// round 17
// speedup vs baseline: 1.0877x; 1.0877x over previous
#include <cuda_runtime.h>
#include <cuda_bf16.h>
#include <cstdint>

#define NC 16
#define HWSZ (512*512)
#define NPIX (4*HWSZ)
#define ST_TOTAL (NPIX/32)      // 32768 super-tiles of 32 pixels
#define GRID 296                // 2 CTAs per SM
#define NW (GRID*8)             // 2368 warps total

// ---------------- folded weights (device globals) ---------------------------
__device__ float g_e1[16 * 64];
__device__ float g_e2[16 * 64];
__device__ float g_c1[128];
__device__ float g_c2[16];
__device__ __nv_bfloat16 g_W1T[128 * 32];   // [j][k]: k<16 -> W0@fw ; k>=16 -> Magg + c1 (bias folded)
__device__ __nv_bfloat16 g_W2T[16 * 144];   // [n][k]: k<128 -> ow@W1 ; k>=128 -> ow@Magg + c2
// pre-swizzled per-lane mma fragments (written by setup_y warp 0)
__device__ __align__(16) uint32_t g_W1F[8][32][8];
__device__ __align__(16) uint32_t g_SF[32][4];

// ---------------- helpers ---------------------------------------------------
__device__ __forceinline__ uint32_t sptr(const void* p) {
    return (uint32_t)__cvta_generic_to_shared(p);
}
__device__ __forceinline__ void ldm4(uint32_t& r0, uint32_t& r1, uint32_t& r2, uint32_t& r3,
                                     uint32_t addr) {
    asm volatile("ldmatrix.sync.aligned.m8n8.x4.shared.b16 {%0,%1,%2,%3}, [%4];"
                 : "=r"(r0), "=r"(r1), "=r"(r2), "=r"(r3) : "r"(addr));
}
__device__ __forceinline__ void mma16816(float* c, const uint32_t* a, uint32_t b0, uint32_t b1) {
    asm volatile("mma.sync.aligned.m16n8k16.row.col.f32.bf16.bf16.f32 "
                 "{%0,%1,%2,%3}, {%4,%5,%6,%7}, {%8,%9}, {%0,%1,%2,%3};"
                 : "+f"(c[0]), "+f"(c[1]), "+f"(c[2]), "+f"(c[3])
                 : "r"(a[0]), "r"(a[1]), "r"(a[2]), "r"(a[3]), "r"(b0), "r"(b1));
}
__device__ __forceinline__ uint32_t pack2(float a, float b) {
    __nv_bfloat162 h = __floats2bfloat162_rn(a, b);
    return *reinterpret_cast<uint32_t*>(&h);
}
__device__ __forceinline__ uint32_t packrelu2(float a, float b) {
    return pack2(fmaxf(a, 0.0f), fmaxf(b, 0.0f));
}
__device__ __forceinline__ float wred(float s) {
    #pragma unroll
    for (int d = 16; d > 0; d >>= 1) s += __shfl_xor_sync(0xffffffffu, s, d);
    return s;
}

// ---------------- setup_x: maximally parallel folds (337 CTAs) --------------
__global__ __launch_bounds__(256)
void setup_x(const float* __restrict__ E,
             const float* __restrict__ aw1, const float* __restrict__ ab1,
             const float* __restrict__ aw2, const float* __restrict__ ab2,
             const float* __restrict__ w0,  const float* __restrict__ b0,
             const float* __restrict__ w1,  const float* __restrict__ b1,
             const float* __restrict__ fw,  const float* __restrict__ fb,
             const float* __restrict__ ow,  const float* __restrict__ ob) {
    const int tid = threadIdx.x;
    const int lane = tid & 31;
    const int w = tid >> 5;
    const int blk = blockIdx.x;

    if (blk < 256) {
        const int wid = (blk << 3) | w;              // 0..2047
        const int which = wid >> 10, i = (wid >> 6) & 15, k = wid & 63;
        const float* __restrict__ wp = which ? aw2 : aw1;
        const float4 ev = *reinterpret_cast<const float4*>(E + i * 128 + 4 * lane);
        const float4 wv = *reinterpret_cast<const float4*>(wp + k * 128 + 4 * lane);
        const float s = wred(ev.x * wv.x + ev.y * wv.y + ev.z * wv.z + ev.w * wv.w);
        if (lane == 0) {
            const float v = fmaxf(s + (which ? ab2 : ab1)[k], 0.0f);
            if (which) g_e2[i * 64 + k] = v; else g_e1[i * 64 + k] = v;
        }
    } else if (blk < 288) {
        // Bw = ow @ W1 -> g_W2T cols 0..127
        const int tg = (blk - 256) * 256 + tid;
        const int o = tg >> 2, sub = tg & 3;
        const int n = o >> 7, d = o & 127;
        const float* __restrict__ owr = ow + n * 128 + sub * 32;
        float s0 = 0.f, s1 = 0.f;
        #pragma unroll 8
        for (int j = 0; j < 32; j += 2) {
            s0 += owr[j]     * w1[(sub * 32 + j)     * 128 + d];
            s1 += owr[j + 1] * w1[(sub * 32 + j + 1) * 128 + d];
        }
        float s = s0 + s1;
        s += __shfl_xor_sync(0xffffffffu, s, 1);
        s += __shfl_xor_sync(0xffffffffu, s, 2);
        if (sub == 0) g_W2T[n * 144 + d] = __float2bfloat16(s);
    } else if (blk < 320) {
        // A = W0 @ fw -> g_W1T cols 0..15
        const int tg = (blk - 288) * 256 + tid;
        const int o = tg >> 2, sub = tg & 3;
        const int j = o >> 4, c = o & 15;
        const float* __restrict__ wr = w0 + j * 128 + sub * 32;
        float s0 = 0.f, s1 = 0.f;
        #pragma unroll 8
        for (int d = 0; d < 32; d += 2) {
            s0 += wr[d]     * fw[(sub * 32 + d)     * 16 + c];
            s1 += wr[d + 1] * fw[(sub * 32 + d + 1) * 16 + c];
        }
        float s = s0 + s1;
        s += __shfl_xor_sync(0xffffffffu, s, 1);
        s += __shfl_xor_sync(0xffffffffu, s, 2);
        if (sub == 0) g_W1T[j * 32 + c] = __float2bfloat16(s);
    } else if (blk < 336) {
        const int j = ((blk - 320) << 3) | w;        // 0..127
        const float4 wv = *reinterpret_cast<const float4*>(&w0[j * 128 + 4 * lane]);
        const float4 fv = *reinterpret_cast<const float4*>(&fb[4 * lane]);
        const float s = wred(wv.x * fv.x + wv.y * fv.y + wv.z * fv.z + wv.w * fv.w);
        if (lane == 0) g_c1[j] = s + b0[j];
    } else {
        for (int r = 0; r < 2; r++) {
            const int n = w * 2 + r;
            const float4 ov = *reinterpret_cast<const float4*>(&ow[n * 128 + 4 * lane]);
            const float4 bv = *reinterpret_cast<const float4*>(&b1[4 * lane]);
            const float s = wred(ov.x * bv.x + ov.y * bv.y + ov.z * bv.z + ov.w * bv.w);
            if (lane == 0) g_c2[n] = s + ob[n];
        }
    }
}

// ---------------- setup_y: adjacency + bias folds + fragment repack ---------
__global__ __launch_bounds__(256)
void setup_y(const float* __restrict__ E, const float* __restrict__ ow) {
    __shared__ float e1s[16][64];
    __shared__ float e2s[16][64];
    __shared__ float adjs[16][16];
    __shared__ float rs[16];
    __shared__ float Maggs[128][16];
    __shared__ __align__(16) __nv_bfloat16 W1s[128][40];
    __shared__ __align__(16) __nv_bfloat16 W2s[16][152];
    const int tid = threadIdx.x;

    for (int i = tid; i < 1024; i += 256) {
        e1s[i >> 6][i & 63] = g_e1[i];
        e2s[i >> 6][i & 63] = g_e2[i];
    }
    __syncthreads();
    {
        const int i = tid >> 4, j = tid & 15;
        float s0 = 0.f, s1 = 0.f, s2 = 0.f, s3 = 0.f;
        #pragma unroll 4
        for (int k = 0; k < 64; k += 4) {
            s0 += e1s[i][k]     * e2s[j][k];
            s1 += e1s[i][k + 1] * e2s[j][k + 1];
            s2 += e1s[i][k + 2] * e2s[j][k + 2];
            s3 += e1s[i][k + 3] * e2s[j][k + 3];
        }
        const float s = (s0 + s1) + (s2 + s3);
        adjs[i][j] = 1.0f / (1.0f + expf(-s)) + ((i == j) ? 1.0f : 0.0f);
    }
    __syncthreads();
    if (tid < 16) {
        float s = 0.0f;
        #pragma unroll
        for (int j = 0; j < 16; j++) s += adjs[tid][j];
        rs[tid] = 1.0f / s;
    }
    __syncthreads();
    // Magg + c1 fold -> W1T cols 16..31 (exact: sum_c p_c = 1); keep Magg for S
    for (int idx = tid; idx < 2048; idx += 256) {
        const int c = idx >> 7, j = idx & 127;
        float s = 0.0f;
        #pragma unroll
        for (int i = 0; i < 16; i++) s += adjs[c][i] * E[i * 128 + j];
        s *= rs[c];
        Maggs[j][c] = s;
        const __nv_bfloat16 hb = __float2bfloat16(s + g_c1[j]);
        W1s[j][16 + c] = hb;
    }
    __syncthreads();
    // S + c2 fold -> W2T cols 128..143
    {
        const int n = tid >> 4, c = tid & 15;
        float s0 = 0.f, s1 = 0.f, s2 = 0.f, s3 = 0.f;
        #pragma unroll 4
        for (int j = 0; j < 128; j += 4) {
            s0 += ow[n * 128 + j]     * Maggs[j][c];
            s1 += ow[n * 128 + j + 1] * Maggs[j + 1][c];
            s2 += ow[n * 128 + j + 2] * Maggs[j + 2][c];
            s3 += ow[n * 128 + j + 3] * Maggs[j + 3][c];
        }
        const __nv_bfloat16 hb = __float2bfloat16((s0 + s1) + (s2 + s3) + g_c2[n]);
        W2s[n][128 + c] = hb;
    }
    // stage setup_x-produced parts (global writes visible via kernel ordering)
    for (int i = tid; i < 2048; i += 256) {          // W1T cols 0..15
        const int j = i >> 4, c = i & 15;
        W1s[j][c] = g_W1T[j * 32 + c];
    }
    for (int i = tid; i < 2048; i += 256) {          // W2T cols 0..127
        const int n = i >> 7, d = i & 127;
        W2s[n][d] = g_W2T[n * 144 + d];
    }
    __syncthreads();
    // write back the fully-assembled W2T (cols 0..143) for refine staging
    for (int i = tid; i < 16 * 144; i += 256) {
        const int n = i / 144, k = i % 144;
        g_W2T[n * 144 + k] = W2s[n][k];
    }

    // ---- warp 0: ldmatrix repack -> per-lane fragment arrays in gmem ----
    if (tid < 32) {
        const int lane = tid;
        const int brow16 = (lane & 7) + ((lane >= 16) ? 8 : 0);
        const int bcol8 = (lane & 8) ? 8 : 0;
        #pragma unroll
        for (int ntp = 0; ntp < 8; ntp++) {
            uint32_t r0, r1, r2, r3;
            ldm4(r0, r1, r2, r3, sptr(&W1s[16 * ntp + brow16][bcol8]));
            g_W1F[ntp][lane][0] = r0; g_W1F[ntp][lane][1] = r1;
            g_W1F[ntp][lane][2] = r2; g_W1F[ntp][lane][3] = r3;
            ldm4(r0, r1, r2, r3, sptr(&W1s[16 * ntp + brow16][16 + bcol8]));
            g_W1F[ntp][lane][4] = r0; g_W1F[ntp][lane][5] = r1;
            g_W1F[ntp][lane][6] = r2; g_W1F[ntp][lane][7] = r3;
        }
        uint32_t r0, r1, r2, r3;
        ldm4(r0, r1, r2, r3, sptr(&W2s[brow16][128 + bcol8]));
        g_SF[lane][0] = r0; g_SF[lane][1] = r1;
        g_SF[lane][2] = r2; g_SF[lane][3] = r3;
    }
}

// ---------------- refine: 32-px super-tiles, in-loop W2 via smem ldm4 -------
__global__ __launch_bounds__(256, 2)
void refine_kernel(const float* __restrict__ logits, float* __restrict__ out,
                   const float* __restrict__ gatep) {
    // per-warp 16ch x 32px fp32 slab, row stride 36 (36 mod 32 = 4 -> frag banks 8t+g, conflict-free)
    __shared__ __align__(16) float wbuf[8][2][16 * 36];   // 36864 B
    __shared__ __align__(16) __nv_bfloat16 W2s[16][152];  //  4864 B  (total 41728 < 48K)

    const int tid = threadIdx.x;
    const int lane = tid & 31;
    const int w = tid >> 5;
    const int t = lane & 3;
    const int g = lane >> 2;
    const int ldr = lane >> 3;       // row offset 0..3 for 128B loads/stores
    const int ldc = (lane & 7) * 4;  // 16B chunk within 128B row

    const float gate = *gatep;

    // stage W2 into smem once (in-loop fragments come from here via ldm4)
    for (int i = tid; i < 16 * 144; i += 256) W2s[i / 144][i % 144] = g_W2T[i];

    // W1/S fragments: one-time LDG from pre-swizzled tables (prologue only)
    uint32_t fW1[8][8];
    #pragma unroll
    for (int kb = 0; kb < 8; kb++) {
        const uint4 u0 = *reinterpret_cast<const uint4*>(&g_W1F[kb][lane][0]);
        const uint4 u1 = *reinterpret_cast<const uint4*>(&g_W1F[kb][lane][4]);
        fW1[kb][0] = u0.x; fW1[kb][1] = u0.y; fW1[kb][2] = u0.z; fW1[kb][3] = u0.w;
        fW1[kb][4] = u1.x; fW1[kb][5] = u1.y; fW1[kb][6] = u1.z; fW1[kb][7] = u1.w;
    }
    uint32_t fS[4];
    {
        const uint4 u = *reinterpret_cast<const uint4*>(&g_SF[lane][0]);
        fS[0] = u.x; fS[1] = u.y; fS[2] = u.z; fS[3] = u.w;
    }
    __syncthreads();   // W2s visible to all warps (only CTA barrier in kernel)

    const int brow16 = (lane & 7) + ((lane >= 16) ? 8 : 0);
    const int bcol8 = (lane & 8) ? 8 : 0;
    const uint32_t w2base = sptr(&W2s[brow16][bcol8]);

    // per-warp prefetch: 16 channel-rows x 128B, 4 cp.async of 16B/lane
    auto prefetch = [&](int st_, int bsel) {
        const int P = st_ << 5;
        const float* __restrict__ src =
            logits + (size_t)(P >> 18) * (NC * HWSZ) + (P & (HWSZ - 1));
        #pragma unroll
        for (int i = 0; i < 4; i++) {
            const int r = 4 * i + ldr;
            const uint32_t d = sptr(&wbuf[w][bsel][r * 36 + ldc]);
            const float* s = src + (size_t)r * HWSZ + ldc;
            asm volatile("cp.async.cg.shared.global [%0], [%1], 16;" :: "r"(d), "l"(s));
        }
        asm volatile("cp.async.commit_group;");
    };

    int st = (blockIdx.x << 3) | w;
    prefetch(st, 0);
    {
        int t1 = st + NW; if (t1 >= ST_TOTAL) t1 = st;
        prefetch(t1, 1);
    }
    int buf = 0;

    for (; st < ST_TOTAL; st += NW) {
        asm volatile("cp.async.wait_group 1;");
        __syncwarp();
        float* __restrict__ B = &wbuf[w][buf][0];

        // ---- two 16-px tiles, processed sequentially ----
        #pragma unroll
        for (int half = 0; half < 2; half++) {
            const int po = half * 16 + g;
            const float l0 = B[(2 * t) * 36 + po],         l1 = B[(2 * t + 1) * 36 + po];
            const float l2 = B[(2 * t) * 36 + po + 8],     l3 = B[(2 * t + 1) * 36 + po + 8];
            const float l4 = B[(2 * t + 8) * 36 + po],     l5 = B[(2 * t + 9) * 36 + po];
            const float l6 = B[(2 * t + 8) * 36 + po + 8], l7 = B[(2 * t + 9) * 36 + po + 8];
            // softmax, no max-sub (logits O(1), fp32-safe, identical)
            const float p0 = __expf(l0), p1 = __expf(l1);
            const float p4 = __expf(l4), p5 = __expf(l5);
            const float q2 = __expf(l2), q3 = __expf(l3);
            const float q6 = __expf(l6), q7 = __expf(l7);
            float sx = (p0 + p1) + (p4 + p5);
            float sy = (q2 + q3) + (q6 + q7);
            sx += __shfl_xor_sync(0xffffffffu, sx, 1);
            sy += __shfl_xor_sync(0xffffffffu, sy, 1);
            sx += __shfl_xor_sync(0xffffffffu, sx, 2);
            sy += __shfl_xor_sync(0xffffffffu, sy, 2);
            const float ix = __fdividef(1.0f, sx);
            const float iy = __fdividef(1.0f, sy);
            uint32_t aL[4], aP[4];
            aL[0] = pack2(l0, l1); aL[1] = pack2(l2, l3);
            aL[2] = pack2(l4, l5); aL[3] = pack2(l6, l7);
            aP[0] = pack2(p0 * ix, p1 * ix); aP[1] = pack2(q2 * iy, q3 * iy);
            aP[2] = pack2(p4 * ix, p5 * ix); aP[3] = pack2(q6 * iy, q7 * iy);

            // GEMM1 -> relu -> GEMM2 (biases pre-folded; W2 frag via smem ldm4)
            float racc[2][4] = {{0.f, 0.f, 0.f, 0.f}, {0.f, 0.f, 0.f, 0.f}};
            mma16816(racc[0], aP, fS[0], fS[1]);
            mma16816(racc[1], aP, fS[2], fS[3]);
            #pragma unroll
            for (int kb = 0; kb < 8; kb++) {
                uint32_t b0, b1, b2, b3;
                ldm4(b0, b1, b2, b3, w2base + 32 * kb);
                float acc0[4] = {0.f, 0.f, 0.f, 0.f};
                float acc1[4] = {0.f, 0.f, 0.f, 0.f};
                mma16816(acc0, aL, fW1[kb][0], fW1[kb][1]);
                mma16816(acc1, aL, fW1[kb][2], fW1[kb][3]);
                mma16816(acc0, aP, fW1[kb][4], fW1[kb][5]);
                mma16816(acc1, aP, fW1[kb][6], fW1[kb][7]);
                uint32_t h[4];
                h[0] = packrelu2(acc0[0], acc0[1]);
                h[1] = packrelu2(acc0[2], acc0[3]);
                h[2] = packrelu2(acc1[0], acc1[1]);
                h[3] = packrelu2(acc1[2], acc1[3]);
                mma16816(racc[0], h, b0, b1);
                mma16816(racc[1], h, b2, b3);
            }

            // epilogue: gate*r + residual (l still live) back into slab
            B[(2 * t) * 36 + po]         = fmaf(gate, racc[0][0], l0);
            B[(2 * t + 1) * 36 + po]     = fmaf(gate, racc[0][1], l1);
            B[(2 * t) * 36 + po + 8]     = fmaf(gate, racc[0][2], l2);
            B[(2 * t + 1) * 36 + po + 8] = fmaf(gate, racc[0][3], l3);
            B[(2 * t + 8) * 36 + po]     = fmaf(gate, racc[1][0], l4);
            B[(2 * t + 9) * 36 + po]     = fmaf(gate, racc[1][1], l5);
            B[(2 * t + 8) * 36 + po + 8] = fmaf(gate, racc[1][2], l6);
            B[(2 * t + 9) * 36 + po + 8] = fmaf(gate, racc[1][3], l7);
        }
        __syncwarp();

        // ---- coalesced store: 16 channel-rows x 128B ----
        {
            const int P = st << 5;
            float* __restrict__ dst =
                out + (size_t)(P >> 18) * (NC * HWSZ) + (P & (HWSZ - 1));
            #pragma unroll
            for (int i = 0; i < 4; i++) {
                const int r = 4 * i + ldr;
                const float4 v = *reinterpret_cast<const float4*>(B + r * 36 + ldc);
                *reinterpret_cast<float4*>(dst + (size_t)r * HWSZ + ldc) = v;
            }
        }

        // refill this slab (contents already consumed into registers/out)
        {
            int n2 = st + 2 * NW; if (n2 >= ST_TOTAL) n2 = st;
            prefetch(n2, buf);
        }
        buf ^= 1;
    }
}

// ---------------- launch -----------------------------------------------------
extern "C" void kernel_launch(void* const* d_in, const int* in_sizes, int n_in,
                              void* d_out, int out_size) {
    const float* logits = (const float*)d_in[0];
    const float* E      = (const float*)d_in[1];
    const float* aw1    = (const float*)d_in[2];
    const float* ab1    = (const float*)d_in[3];
    const float* aw2    = (const float*)d_in[4];
    const float* ab2    = (const float*)d_in[5];
    const float* w0     = (const float*)d_in[6];
    const float* b0     = (const float*)d_in[7];
    const float* w1     = (const float*)d_in[8];
    const float* b1     = (const float*)d_in[9];
    const float* fw     = (const float*)d_in[10];
    const float* fb     = (const float*)d_in[11];
    const float* ow     = (const float*)d_in[12];
    const float* ob     = (const float*)d_in[13];
    const float* gate   = (const float*)d_in[14];
    float* out = (float*)d_out;

    setup_x<<<337, 256>>>(E, aw1, ab1, aw2, ab2, w0, b0, w1, b1, fw, fb, ow, ob);
    setup_y<<<1, 256>>>(E, ow);
    refine_kernel<<<GRID, 256>>>(logits, out, gate);
}